// round 1
// baseline (speedup 1.0000x reference)
#include <cuda_runtime.h>

#define Bb 8
#define Tt 2048
#define Cc 1024
#define Hh 64
#define BT (Bb*Tt)

// scratch for projected q,k,v (4 MB each) — __device__ globals per allocation rules
__device__ float g_q[BT*Hh];
__device__ float g_k[BT*Hh];
__device__ float g_v[BT*Hh];

__device__ __forceinline__ float fast_exp2(float x){
    float y;
    asm("ex2.approx.ftz.f32 %0, %1;" : "=f"(y) : "f"(x));
    return y;
}

// ---------------------------------------------------------------------------
// Projection: out[BT x 64] = x[BT x 1024] @ W[1024 x 64], one of 3 per blockIdx.y
// 128x64 output tile per block, 128 threads, 8x8 register tile per thread.
// ---------------------------------------------------------------------------
__global__ __launch_bounds__(128) void proj_kernel(
    const float* __restrict__ x,
    const float* __restrict__ Wk,
    const float* __restrict__ Wq,
    const float* __restrict__ Wv)
{
    const int m = blockIdx.y;
    const float* __restrict__ W = (m == 0) ? Wk : (m == 1) ? Wq : Wv;
    float* __restrict__ out = (m == 0) ? g_k : (m == 1) ? g_q : g_v;

    const int row0 = blockIdx.x * 128;
    const int tid = threadIdx.x;
    const int tr = tid >> 3;   // 0..15
    const int tc = tid & 7;    // 0..7

    __shared__ float xs[128][17];   // pad 17 -> conflict-free a[i] reads
    __shared__ float ws[16][64];

    float acc[8][8];
#pragma unroll
    for (int i = 0; i < 8; i++)
#pragma unroll
        for (int j = 0; j < 8; j++) acc[i][j] = 0.f;

    for (int kc = 0; kc < Cc; kc += 16) {
        // load x chunk: 128x16 floats = 512 float4, 4 per thread
#pragma unroll
        for (int u = 0; u < 4; u++) {
            int f  = tid + 128 * u;        // float4 index
            int rr = f >> 2;               // 4 float4 per row
            int cc = (f & 3) * 4;
            float4 v = *(const float4*)&x[(size_t)(row0 + rr) * Cc + kc + cc];
            xs[rr][cc + 0] = v.x; xs[rr][cc + 1] = v.y;
            xs[rr][cc + 2] = v.z; xs[rr][cc + 3] = v.w;
        }
        // load W chunk: 16x64 floats = 256 float4, 2 per thread
#pragma unroll
        for (int u = 0; u < 2; u++) {
            int f  = tid + 128 * u;
            int rr = f >> 4;               // 16 float4 per row
            int cc = (f & 15) * 4;
            *(float4*)&ws[rr][cc] = *(const float4*)&W[(size_t)(kc + rr) * Hh + cc];
        }
        __syncthreads();
#pragma unroll
        for (int k = 0; k < 16; k++) {
            float a[8], b[8];
#pragma unroll
            for (int i = 0; i < 8; i++) a[i] = xs[tr + 16 * i][k];
#pragma unroll
            for (int j = 0; j < 8; j++) b[j] = ws[k][tc + 8 * j];
#pragma unroll
            for (int i = 0; i < 8; i++)
#pragma unroll
                for (int j = 0; j < 8; j++)
                    acc[i][j] += a[i] * b[j];
        }
        __syncthreads();
    }
#pragma unroll
    for (int i = 0; i < 8; i++)
#pragma unroll
        for (int j = 0; j < 8; j++)
            out[(size_t)(row0 + tr + 16 * i) * Hh + tc + 8 * j] = acc[i][j];
}

// ---------------------------------------------------------------------------
// Flash attention: BM=BN=64, 128 threads (2 threads per query row, 32 dims each).
// grid (T/64, B)
// ---------------------------------------------------------------------------
__global__ __launch_bounds__(128) void attn_kernel(float* __restrict__ out)
{
    const int b    = blockIdx.y;
    const int q0   = blockIdx.x * 64;
    const int tid  = threadIdx.x;
    const int r    = tid >> 1;      // query row in tile: 0..63
    const int half = tid & 1;       // which 32 head dims
    const int doff = half * 32;

    __shared__ float Ks[64 * 64];
    __shared__ float Vs[64 * 64];
    __shared__ float S[64 * 65];    // padded: phase-2 reads stride rows

    // softmax scale (1/sqrt(64)) folded with log2(e) so we can use ex2.approx
    const float scale = 0.125f * 1.44269504088896340736f;

    float q[32];
    {
        const float* qp = &g_q[((size_t)b * Tt + q0 + r) * Hh + doff];
#pragma unroll
        for (int d4 = 0; d4 < 8; d4++) {
            float4 v = *(const float4*)&qp[d4 * 4];
            q[d4 * 4 + 0] = v.x; q[d4 * 4 + 1] = v.y;
            q[d4 * 4 + 2] = v.z; q[d4 * 4 + 3] = v.w;
        }
    }
    float acc[32];
#pragma unroll
    for (int d = 0; d < 32; d++) acc[d] = 0.f;
    float m = -1e30f, l = 0.f;

    for (int n0 = 0; n0 <= q0; n0 += 64) {
        __syncthreads();   // previous tile's smem reads done
        {
            const float4* kp = (const float4*)&g_k[((size_t)b * Tt + n0) * Hh];
            const float4* vp = (const float4*)&g_v[((size_t)b * Tt + n0) * Hh];
#pragma unroll
            for (int u = 0; u < 8; u++) {
                int f = tid + 128 * u;        // 1024 float4 per tile
                ((float4*)Ks)[f] = kp[f];
                ((float4*)Vs)[f] = vp[f];
            }
        }
        __syncthreads();

        // phase 1: scores for this tile, tile max
        float mt = -1e30f;
#pragma unroll 4
        for (int j = 0; j < 64; j++) {
            float p0 = 0.f, p1 = 0.f, p2 = 0.f, p3 = 0.f;
            const float* kr = &Ks[j * 64 + doff];
#pragma unroll
            for (int d4 = 0; d4 < 8; d4++) {
                float4 kv = *(const float4*)&kr[d4 * 4];
                p0 += q[d4 * 4 + 0] * kv.x;
                p1 += q[d4 * 4 + 1] * kv.y;
                p2 += q[d4 * 4 + 2] * kv.z;
                p3 += q[d4 * 4 + 3] * kv.w;
            }
            float s = (p0 + p1) + (p2 + p3);
            s += __shfl_xor_sync(0xffffffffu, s, 1);   // combine the two halves
            s *= scale;
            if (n0 + j > q0 + r) s = -1e30f;           // causal mask
            S[r * 65 + j] = s;                          // both halves write same value
            mt = fmaxf(mt, s);
        }
        float m_new = fmaxf(m, mt);
        float corr  = fast_exp2(m - m_new);
        l *= corr;
#pragma unroll
        for (int d = 0; d < 32; d++) acc[d] *= corr;

        // phase 2: exp + PV
#pragma unroll 2
        for (int j = 0; j < 64; j++) {
            float p = fast_exp2(S[r * 65 + j] - m_new);
            l += p;
            const float* vr = &Vs[j * 64 + doff];
#pragma unroll
            for (int d4 = 0; d4 < 8; d4++) {
                float4 vv = *(const float4*)&vr[d4 * 4];
                acc[d4 * 4 + 0] += p * vv.x;
                acc[d4 * 4 + 1] += p * vv.y;
                acc[d4 * 4 + 2] += p * vv.z;
                acc[d4 * 4 + 3] += p * vv.w;
            }
        }
        m = m_new;
    }

    const float inv = 1.0f / l;
    float* op = &out[((size_t)b * Tt + q0 + r) * Hh + doff];
#pragma unroll
    for (int d4 = 0; d4 < 8; d4++) {
        float4 v;
        v.x = acc[d4 * 4 + 0] * inv;
        v.y = acc[d4 * 4 + 1] * inv;
        v.z = acc[d4 * 4 + 2] * inv;
        v.w = acc[d4 * 4 + 3] * inv;
        *(float4*)&op[d4 * 4] = v;
    }
}

extern "C" void kernel_launch(void* const* d_in, const int* in_sizes, int n_in,
                              void* d_out, int out_size)
{
    const float* x  = (const float*)d_in[0];
    const float* Wk = (const float*)d_in[1];
    const float* Wq = (const float*)d_in[2];
    const float* Wv = (const float*)d_in[3];
    float* out = (float*)d_out;

    dim3 pg(BT / 128, 3);
    proj_kernel<<<pg, 128>>>(x, Wk, Wq, Wv);

    dim3 ag(Tt / 64, Bb);
    attn_kernel<<<ag, 128>>>(out);
}